// round 4
// baseline (speedup 1.0000x reference)
#include <cuda_runtime.h>
#include <math.h>

#define MAXB 16384

// ---------------- device scratch (no allocations allowed) ----------------
__device__ unsigned g_packed[MAXB * 66];   // bit x of word = sign(x[b][c][y][x])>=0, word index b*66 + c*22 + y
__device__ unsigned g_w1[32];              // 27-bit key per oc, bit = c*9+dy*3+dx
__device__ int      g_T1[32];
__device__ unsigned g_w2[288];             // [oc*9 + dy*3+dx], bit = input channel
__device__ int      g_T2[32];
__device__ unsigned g_w3[576];             // [oc*9 + dy*3+dx], bit = input channel
__device__ int      g_T3[64];
__device__ unsigned g_fc1[256];            // [j*2 + half], bit k = sign(w_fc1[j][half*32+k])
__device__ float    g_a4[128], g_c4[128];  // bn4 folded: h = clamp(a*s + c)
__device__ float    g_head[12];            // a5[2], c5[2], a6[4], c6[4]

// ---------------- bn threshold helper ----------------
__device__ __forceinline__ double bn_thresh_t(const float* bn, int C, int c) {
    // bn rows: gamma, beta, mean, var.  sign(bn(s)) >= 0  <=>  s >= m - b*sqrt(v+eps)/g   (g > 0)
    double g = bn[c], b = bn[C + c], m = bn[2 * C + c], v = bn[3 * C + c];
    return m - b * sqrt(v + 1e-5) / g;
}

// ---------------- fused pack (blocks [0, npack)) + prep (blocks [npack, npack+4)) ----------------
__global__ void pack_prep_kernel(const float4* __restrict__ x4, int B, int npack,
                                 const float* __restrict__ w1, const float* __restrict__ w2,
                                 const float* __restrict__ w3, const float* __restrict__ wfc1,
                                 const float* __restrict__ bn1, const float* __restrict__ bn2,
                                 const float* __restrict__ bn3, const float* __restrict__ bn4,
                                 const float* __restrict__ bn5, const float* __restrict__ bn6) {
    if (blockIdx.x < (unsigned)npack) {
        __shared__ __align__(16) unsigned char sb[8 * 1452];
        int s0 = blockIdx.x * 8;
        int nsamp = B - s0; if (nsamp > 8) nsamp = 8;
        if (nsamp <= 0) return;
        const float4* p = x4 + (size_t)s0 * 363;       // 1452/4 = 363 float4 per sample
        int n4 = nsamp * 363;
        for (int i = threadIdx.x; i < n4; i += 256) {
            float4 v = p[i];
            uchar4 c;
            c.x = (v.x >= 0.f); c.y = (v.y >= 0.f); c.z = (v.z >= 0.f); c.w = (v.w >= 0.f);
            reinterpret_cast<uchar4*>(sb)[i] = c;
        }
        __syncthreads();
        int nw = nsamp * 66;
        for (int w = threadIdx.x; w < nw; w += 256) {
            const unsigned char* q = sb + (w / 66) * 1452 + (w % 66) * 22;
            unsigned word = 0;
#pragma unroll
            for (int i = 0; i < 22; ++i) word |= ((unsigned)q[i]) << i;
            g_packed[(size_t)s0 * 66 + w] = word;
        }
        return;
    }

    // ---- prep portion (4 CTAs, concurrent with pack) ----
    const int t = (blockIdx.x - npack) * 256 + threadIdx.x;
    const int nt = 4 * 256;
    for (int oc = t; oc < 32; oc += nt) {
        unsigned w = 0;
        for (int k = 0; k < 27; ++k) if (w1[oc * 27 + k] >= 0.f) w |= 1u << k;
        g_w1[oc] = w;
        g_T1[oc] = (int)floor((27.0 - bn_thresh_t(bn1, 32, oc)) * 0.5);   // keep iff cnt_disagree <= T
        g_T2[oc] = (int)floor((288.0 - bn_thresh_t(bn2, 32, oc)) * 0.5);
    }
    for (int i = t; i < 288; i += nt) {
        int oc = i / 9, p = i % 9; unsigned w = 0;
        for (int c = 0; c < 32; ++c) if (w2[(oc * 32 + c) * 9 + p] >= 0.f) w |= 1u << c;
        g_w2[i] = w;
    }
    for (int i = t; i < 576; i += nt) {
        int oc = i / 9, p = i % 9; unsigned w = 0;
        for (int c = 0; c < 32; ++c) if (w3[(oc * 32 + c) * 9 + p] >= 0.f) w |= 1u << c;
        g_w3[i] = w;
    }
    for (int oc = t; oc < 64; oc += nt)
        g_T3[oc] = (int)floor((288.0 - bn_thresh_t(bn3, 64, oc)) * 0.5);
    for (int i = t; i < 256; i += nt) {
        int j = i >> 1, h = i & 1; unsigned w = 0;
        for (int k = 0; k < 32; ++k) if (wfc1[j * 64 + h * 32 + k] >= 0.f) w |= 1u << k;
        g_fc1[i] = w;
    }
    for (int j = t; j < 128; j += nt) {
        float g = bn4[j], b = bn4[128 + j], m = bn4[256 + j], v = bn4[384 + j];
        float inv = g * rsqrtf(v + 1e-5f);
        g_a4[j] = inv; g_c4[j] = b - m * inv;
    }
    if (t < 2) {
        float g = bn5[t], b = bn5[2 + t], m = bn5[4 + t], v = bn5[6 + t];
        float inv = g * rsqrtf(v + 1e-5f);
        g_head[t] = inv; g_head[2 + t] = b - m * inv;
    }
    if (t >= 4 && t < 8) {
        int q = t - 4;
        float g = bn6[q], b = bn6[4 + q], m = bn6[8 + q], v = bn6[12 + q];
        float inv = g * rsqrtf(v + 1e-5f);
        g_head[4 + q] = inv; g_head[8 + q] = b - m * inv;
    }
}

// ---------------- main fused network: 8 threads (an "octet") per sample ----------------
// Register-lean layout: conv2 splits by pooled CELL (2 cells x 32 oc per lane),
// results staged through shared s_s2, so no 40-word row cache and no S2 shuffles.
__global__ void __launch_bounds__(128, 8) main_kernel(
    const float* __restrict__ wfc2, const float* __restrict__ wfc3,
    float* __restrict__ out, int B) {

    __shared__ unsigned s_w1[32];  __shared__ int s_T1[32];
    __shared__ unsigned s_w2[288]; __shared__ int s_T2[32];
    __shared__ unsigned s_w3[576]; __shared__ int s_T3[64];
    __shared__ unsigned s_fc1[256];
    __shared__ float s_a4[128], s_c4[128];
    __shared__ float s_f2[256], s_f3[512];
    __shared__ float s_head[12];
    __shared__ unsigned s_pin[16][66];  // packed input per sample slot
    __shared__ unsigned s_s1[16][100];  // stage-1 pooled bits, word (py*10+px), bit = oc
    __shared__ unsigned s_s2[16][16];   // stage-2 pooled bits, word (pr*4+pc), bit = oc

    const int tid = threadIdx.x;
    for (int i = tid; i < 32; i += 128) { s_w1[i] = g_w1[i]; s_T1[i] = g_T1[i]; s_T2[i] = g_T2[i]; }
    for (int i = tid; i < 288; i += 128) s_w2[i] = g_w2[i];
    for (int i = tid; i < 576; i += 128) s_w3[i] = g_w3[i];
    for (int i = tid; i < 64; i += 128) s_T3[i] = g_T3[i];
    for (int i = tid; i < 256; i += 128) { s_fc1[i] = g_fc1[i]; s_f2[i] = wfc2[i]; }
    for (int i = tid; i < 128; i += 128) { s_a4[i] = g_a4[i]; s_c4[i] = g_c4[i]; }
    for (int i = tid; i < 512; i += 128) s_f3[i] = wfc3[i];
    if (tid < 12) s_head[tid] = g_head[tid];
    __syncthreads();

    const int gt = blockIdx.x * 128 + tid;
    const int s = gt >> 3;        // sample
    const int r = gt & 7;         // lane within octet
    if (s >= B) return;           // B multiple of 16 -> whole warps exit together
    const int sl = tid >> 3;      // sample slot in CTA (0..15)

    // cooperative load of this sample's packed bits into shared
    for (int i = r; i < 66; i += 8) s_pin[sl][i] = g_packed[(size_t)s * 66 + i];
    __syncwarp();

    const unsigned* __restrict__ pin = s_pin[sl];
    unsigned* s1 = s_s1[sl];

    // ---- conv1 (27-term XNOR) + threshold + pool(min) -> s1[10][10], bit = oc ----
    for (int py = 0; py < 10; ++py) {
        unsigned rows[12];
#pragma unroll
        for (int c = 0; c < 3; ++c)
#pragma unroll
            for (int k = 0; k < 4; ++k) rows[c * 4 + k] = pin[c * 22 + 2 * py + k];
        // lane owns cells with (py*10+px) % 8 == r  ->  px ≡ (r + 6*py) (mod 8)
        int px0 = (r + 6 * py) & 7;
        for (int px = px0; px < 10; px += 8) {
            unsigned key[4];
#pragma unroll
            for (int yy = 0; yy < 2; ++yy)
#pragma unroll
                for (int xx = 0; xx < 2; ++xx) {
                    int x0 = 2 * px + xx;
                    unsigned k = 0;
#pragma unroll
                    for (int c = 0; c < 3; ++c)
#pragma unroll
                        for (int dy = 0; dy < 3; ++dy)
                            k |= ((rows[c * 4 + yy + dy] >> x0) & 7u) << (c * 9 + dy * 3);
                    key[yy * 2 + xx] = k;
                }
            unsigned acc = 0;
#pragma unroll
            for (int oc = 0; oc < 32; ++oc) {
                unsigned w = s_w1[oc];
                int m = min(min((int)__popc(key[0] ^ w), (int)__popc(key[1] ^ w)),
                            min((int)__popc(key[2] ^ w), (int)__popc(key[3] ^ w)));
                acc |= (m <= s_T1[oc]) ? (1u << oc) : 0u;
            }
            s1[py * 10 + px] = acc;
        }
    }
    __syncwarp();

    // ---- conv2 (288-term): lane owns pooled row pr = r>>1, cells (pcb, pcb+1), all 32 oc ----
    {
        const int pr = r >> 1;            // 0..3
        const int pcb = (r & 1) * 2;      // 0 or 2
        unsigned R[4][6];                 // rows 2pr..2pr+3, cols 2*pcb .. 2*pcb+5
#pragma unroll
        for (int y = 0; y < 4; ++y)
#pragma unroll
            for (int x = 0; x < 6; ++x) R[y][x] = s1[(2 * pr + y) * 10 + 2 * pcb + x];
        unsigned acc0 = 0u, acc1 = 0u;
#pragma unroll 2
        for (int oc = 0; oc < 32; ++oc) {
            unsigned w[9];
#pragma unroll
            for (int j = 0; j < 9; ++j) w[j] = s_w2[oc * 9 + j];
            int T = s_T2[oc];
#pragma unroll
            for (int cell = 0; cell < 2; ++cell) {
                int c0 = 0, c1 = 0, c2 = 0, c3 = 0;
#pragma unroll
                for (int dy = 0; dy < 3; ++dy)
#pragma unroll
                    for (int dx = 0; dx < 3; ++dx) {
                        unsigned ww = w[dy * 3 + dx];
                        c0 += __popc(R[dy][2 * cell + dx] ^ ww);
                        c1 += __popc(R[dy][2 * cell + dx + 1] ^ ww);
                        c2 += __popc(R[dy + 1][2 * cell + dx] ^ ww);
                        c3 += __popc(R[dy + 1][2 * cell + dx + 1] ^ ww);
                    }
                int m = min(min(c0, c1), min(c2, c3));
                if (cell == 0) acc0 |= (m <= T) ? (1u << oc) : 0u;
                else           acc1 |= (m <= T) ? (1u << oc) : 0u;
            }
        }
        s_s2[sl][pr * 4 + pcb]     = acc0;
        s_s2[sl][pr * 4 + pcb + 1] = acc1;
    }
    __syncwarp();

    // ---- conv3 (288-term, 64 oc; 8 per lane) + threshold + pool -> 64 bits (a0,a1) ----
    unsigned S2[16];
#pragma unroll
    for (int i = 0; i < 16; ++i) S2[i] = s_s2[sl][i];

    unsigned p0 = 0u, p1 = 0u;
    const int ocb3 = r * 8;
#pragma unroll 1
    for (int k = 0; k < 8; ++k) {
        int oc = ocb3 + k;
        unsigned w[9];
#pragma unroll
        for (int j = 0; j < 9; ++j) w[j] = s_w3[oc * 9 + j];
        int c0 = 0, c1 = 0, c2 = 0, c3 = 0;
#pragma unroll
        for (int dy = 0; dy < 3; ++dy)
#pragma unroll
            for (int dx = 0; dx < 3; ++dx) {
                unsigned ww = w[dy * 3 + dx];
                c0 += __popc(S2[dy * 4 + dx] ^ ww);
                c1 += __popc(S2[dy * 4 + dx + 1] ^ ww);
                c2 += __popc(S2[(dy + 1) * 4 + dx] ^ ww);
                c3 += __popc(S2[(dy + 1) * 4 + dx + 1] ^ ww);
            }
        int m = min(min(c0, c1), min(c2, c3));
        unsigned mbit = (m <= s_T3[oc]) ? (1u << (oc & 31)) : 0u;
        if (r < 4) p0 |= mbit; else p1 |= mbit;
    }
    unsigned a0 = p0, a1 = p1;
    a0 |= __shfl_xor_sync(0xFFFFFFFFu, a0, 1); a0 |= __shfl_xor_sync(0xFFFFFFFFu, a0, 2);
    a0 |= __shfl_xor_sync(0xFFFFFFFFu, a0, 4);
    a1 |= __shfl_xor_sync(0xFFFFFFFFu, a1, 1); a1 |= __shfl_xor_sync(0xFFFFFFFFu, a1, 2);
    a1 |= __shfl_xor_sync(0xFFFFFFFFu, a1, 4);

    // ---- fc1 (binary 64-dot) + bn4 + hardtanh, fused with the two float heads ----
    float t0 = 0.f, t1 = 0.f, u0 = 0.f, u1 = 0.f, u2 = 0.f, u3 = 0.f;
    const int jb = r * 16;
#pragma unroll 4
    for (int k = 0; k < 16; ++k) {
        int j = jb + k;
        int cnt = __popc(a0 ^ s_fc1[2 * j]) + __popc(a1 ^ s_fc1[2 * j + 1]);
        float sv = (float)(64 - 2 * cnt);
        float h = fminf(1.f, fmaxf(-1.f, fmaf(sv, s_a4[j], s_c4[j])));
        t0 = fmaf(h, s_f2[j], t0);
        t1 = fmaf(h, s_f2[128 + j], t1);
        u0 = fmaf(h, s_f3[j], u0);
        u1 = fmaf(h, s_f3[128 + j], u1);
        u2 = fmaf(h, s_f3[256 + j], u2);
        u3 = fmaf(h, s_f3[384 + j], u3);
    }
#pragma unroll
    for (int d = 1; d < 8; d <<= 1) {
        t0 += __shfl_xor_sync(0xFFFFFFFFu, t0, d);
        t1 += __shfl_xor_sync(0xFFFFFFFFu, t1, d);
        u0 += __shfl_xor_sync(0xFFFFFFFFu, u0, d);
        u1 += __shfl_xor_sync(0xFFFFFFFFu, u1, d);
        u2 += __shfl_xor_sync(0xFFFFFFFFu, u2, d);
        u3 += __shfl_xor_sync(0xFFFFFFFFu, u3, d);
    }
    if (r == 0) {
        float z0 = fmaf(t0, s_head[0], s_head[2]);
        float z1 = fmaf(t1, s_head[1], s_head[3]);
        float mx = fmaxf(z0, z1);
        float e0 = expf(z0 - mx), e1 = expf(z1 - mx);
        float is = 1.f / (e0 + e1);
        out[2 * s]     = e0 * is;
        out[2 * s + 1] = e1 * is;
        float* o2 = out + (size_t)2 * B;
        o2[4 * s]     = fmaf(u0, s_head[4], s_head[8]);
        o2[4 * s + 1] = fmaf(u1, s_head[5], s_head[9]);
        o2[4 * s + 2] = fmaf(u2, s_head[6], s_head[10]);
        o2[4 * s + 3] = fmaf(u3, s_head[7], s_head[11]);
    }
}

// ---------------- launch ----------------
extern "C" void kernel_launch(void* const* d_in, const int* in_sizes, int n_in,
                              void* d_out, int out_size) {
    (void)n_in; (void)out_size;
    const float* x    = (const float*)d_in[0];
    const float* w1   = (const float*)d_in[1];
    const float* w2   = (const float*)d_in[2];
    const float* w3   = (const float*)d_in[3];
    const float* wfc1 = (const float*)d_in[4];
    const float* wfc2 = (const float*)d_in[5];
    const float* wfc3 = (const float*)d_in[6];
    const float* bn1  = (const float*)d_in[7];
    const float* bn2  = (const float*)d_in[8];
    const float* bn3  = (const float*)d_in[9];
    const float* bn4  = (const float*)d_in[10];
    const float* bn5  = (const float*)d_in[11];
    const float* bn6  = (const float*)d_in[12];

    int B = in_sizes[0] / 1452;  // 3*22*22
    if (B > MAXB) B = MAXB;

    int npack = (B + 7) / 8;
    pack_prep_kernel<<<npack + 4, 256>>>((const float4*)x, B, npack,
                                         w1, w2, w3, wfc1, bn1, bn2, bn3, bn4, bn5, bn6);
    main_kernel<<<(B * 8 + 127) / 128, 128>>>(wfc2, wfc3, (float*)d_out, B);
}

// round 5
// speedup vs baseline: 1.0413x; 1.0413x over previous
#include <cuda_runtime.h>
#include <math.h>

#define MAXB 16384

// ---------------- device scratch (no allocations allowed) ----------------
__device__ unsigned g_w1[32];              // 27-bit key per oc, bit = c*9+dy*3+dx
__device__ int      g_T1[32];
__device__ unsigned g_w2[288];             // [oc*9 + dy*3+dx], bit = input channel
__device__ int      g_T2[32];
__device__ unsigned g_w3[576];             // [oc*9 + dy*3+dx], bit = input channel
__device__ int      g_T3[64];
__device__ unsigned g_fc1[256];            // [j*2 + half], bit k = sign(w_fc1[j][half*32+k])
__device__ float    g_a4[128], g_c4[128];  // bn4 folded: h = clamp(a*s + c)
__device__ float    g_head[12];            // a5[2], c5[2], a6[4], c6[4]

// ---------------- bn threshold helper ----------------
__device__ __forceinline__ double bn_thresh_t(const float* bn, int C, int c) {
    // bn rows: gamma, beta, mean, var.  sign(bn(s)) >= 0  <=>  s >= m - b*sqrt(v+eps)/g   (g > 0)
    double g = bn[c], b = bn[C + c], m = bn[2 * C + c], v = bn[3 * C + c];
    return m - b * sqrt(v + 1e-5) / g;
}

// ---------------- prep: weight packing + threshold folding (8 CTAs) ----------------
__global__ void prep_kernel(const float* __restrict__ w1, const float* __restrict__ w2,
                            const float* __restrict__ w3, const float* __restrict__ wfc1,
                            const float* __restrict__ bn1, const float* __restrict__ bn2,
                            const float* __restrict__ bn3, const float* __restrict__ bn4,
                            const float* __restrict__ bn5, const float* __restrict__ bn6) {
    const int t = blockIdx.x * 256 + threadIdx.x;
    const int nt = 8 * 256;
    for (int oc = t; oc < 32; oc += nt) {
        unsigned w = 0;
        for (int k = 0; k < 27; ++k) if (w1[oc * 27 + k] >= 0.f) w |= 1u << k;
        g_w1[oc] = w;
        g_T1[oc] = (int)floor((27.0 - bn_thresh_t(bn1, 32, oc)) * 0.5);   // keep iff cnt_disagree <= T
        g_T2[oc] = (int)floor((288.0 - bn_thresh_t(bn2, 32, oc)) * 0.5);
    }
    for (int i = t; i < 288; i += nt) {
        int oc = i / 9, p = i % 9; unsigned w = 0;
        for (int c = 0; c < 32; ++c) if (w2[(oc * 32 + c) * 9 + p] >= 0.f) w |= 1u << c;
        g_w2[i] = w;
    }
    for (int i = t; i < 576; i += nt) {
        int oc = i / 9, p = i % 9; unsigned w = 0;
        for (int c = 0; c < 32; ++c) if (w3[(oc * 32 + c) * 9 + p] >= 0.f) w |= 1u << c;
        g_w3[i] = w;
    }
    for (int oc = t; oc < 64; oc += nt)
        g_T3[oc] = (int)floor((288.0 - bn_thresh_t(bn3, 64, oc)) * 0.5);
    for (int i = t; i < 256; i += nt) {
        int j = i >> 1, h = i & 1; unsigned w = 0;
        for (int k = 0; k < 32; ++k) if (wfc1[j * 64 + h * 32 + k] >= 0.f) w |= 1u << k;
        g_fc1[i] = w;
    }
    for (int j = t; j < 128; j += nt) {
        float g = bn4[j], b = bn4[128 + j], m = bn4[256 + j], v = bn4[384 + j];
        float inv = g * rsqrtf(v + 1e-5f);
        g_a4[j] = inv; g_c4[j] = b - m * inv;
    }
    if (t < 2) {
        float g = bn5[t], b = bn5[2 + t], m = bn5[4 + t], v = bn5[6 + t];
        float inv = g * rsqrtf(v + 1e-5f);
        g_head[t] = inv; g_head[2 + t] = b - m * inv;
    }
    if (t >= 4 && t < 8) {
        int q = t - 4;
        float g = bn6[q], b = bn6[4 + q], m = bn6[8 + q], v = bn6[12 + q];
        float inv = g * rsqrtf(v + 1e-5f);
        g_head[4 + q] = inv; g_head[8 + q] = b - m * inv;
    }
}

// ---------------- carry-save adder popcount (Harley-Seal, exact) ----------------
__device__ __forceinline__ void CSA(unsigned& s, unsigned& c, unsigned a, unsigned b, unsigned d) {
    unsigned t = a ^ b;
    s = t ^ d;
    c = (a & b) | (d & t);
}
__device__ __forceinline__ int popc9(unsigned x0, unsigned x1, unsigned x2,
                                     unsigned x3, unsigned x4, unsigned x5,
                                     unsigned x6, unsigned x7, unsigned x8) {
    unsigned s1, c1, s2, c2, s3, c3, s4, c4, s5, c5;
    CSA(s1, c1, x0, x1, x2);
    CSA(s2, c2, x3, x4, x5);
    CSA(s3, c3, x6, x7, x8);
    CSA(s4, c4, s1, s2, s3);
    CSA(s5, c5, c1, c2, c3);
    return __popc(s4) + 2 * (__popc(c4) + __popc(s5)) + 4 * __popc(c5);
}

// ---------------- main fused network: 8 threads (an "octet") per sample ----------------
// Includes input binarize+pack via warp ballot (no separate pack pass).
__global__ void __launch_bounds__(128, 8) main_kernel(
    const float* __restrict__ x,
    const float* __restrict__ wfc2, const float* __restrict__ wfc3,
    float* __restrict__ out, int B) {

    __shared__ unsigned s_w1[32];  __shared__ int s_T1[32];
    __shared__ unsigned s_w2[288]; __shared__ int s_T2[32];
    __shared__ unsigned s_w3[576]; __shared__ int s_T3[64];
    __shared__ unsigned s_fc1[256];
    __shared__ float s_a4[128], s_c4[128];
    __shared__ float s_f2[256], s_f3[512];
    __shared__ float s_head[12];
    __shared__ unsigned s_pin[16][66];  // packed input rows per sample slot
    __shared__ unsigned s_s1[16][100];  // (a) ballot bitstream (46 words), then (b) stage-1 pooled bits
    __shared__ unsigned s_s2[16][16];   // stage-2 pooled bits, word (pr*4+pc), bit = oc

    const int tid = threadIdx.x;
    for (int i = tid; i < 32; i += 128) { s_w1[i] = g_w1[i]; s_T1[i] = g_T1[i]; s_T2[i] = g_T2[i]; }
    for (int i = tid; i < 288; i += 128) s_w2[i] = g_w2[i];
    for (int i = tid; i < 576; i += 128) s_w3[i] = g_w3[i];
    for (int i = tid; i < 64; i += 128) s_T3[i] = g_T3[i];
    for (int i = tid; i < 256; i += 128) { s_fc1[i] = g_fc1[i]; s_f2[i] = wfc2[i]; }
    for (int i = tid; i < 128; i += 128) { s_a4[i] = g_a4[i]; s_c4[i] = g_c4[i]; }
    for (int i = tid; i < 512; i += 128) s_f3[i] = wfc3[i];
    if (tid < 12) s_head[tid] = g_head[tid];
    __syncthreads();

    const int lane = tid & 31;
    const int base = blockIdx.x * 16;

    // ---- binarize + pack: each warp packs its 4 samples (coalesced loads + ballot) ----
    for (int ss = 0; ss < 4; ++ss) {
        int slot = (tid >> 5) * 4 + ss;
        int samp = base + slot;
        if (samp >= B) break;                       // uniform within warp
        const float* xs = x + (size_t)samp * 1452;
        unsigned* dst = s_s1[slot];                 // 46-word bitstream staging
        for (int j0 = 0; j0 < 46; j0 += 8) {
            float v[8];
#pragma unroll
            for (int k = 0; k < 8; ++k) {
                int idx = (j0 + k) * 32 + lane;
                v[k] = (idx < 1452) ? xs[idx] : -1.f;
            }
#pragma unroll
            for (int k = 0; k < 8; ++k) {
                unsigned b = __ballot_sync(0xFFFFFFFFu, v[k] >= 0.f);
                if (lane == k && (j0 + k) < 46) dst[j0 + k] = b;
            }
        }
    }
    __syncwarp();

    const int gt = blockIdx.x * 128 + tid;
    const int s = gt >> 3;        // sample
    const int r = gt & 7;         // lane within octet
    if (s >= B) return;           // B multiple of 16 -> whole warps exit together
    const int sl = tid >> 3;      // sample slot in CTA (0..15)

    // re-align bitstream to 22-bit row words: word i covers bits [22i, 22i+22)
    {
        const unsigned* st = s_s1[sl];
        for (int i = r; i < 66; i += 8) {
            int off = i * 22;
            s_pin[sl][i] = __funnelshift_r(st[off >> 5], st[(off >> 5) + 1], off & 31) & 0x3FFFFFu;
        }
    }
    __syncwarp();

    const unsigned* __restrict__ pin = s_pin[sl];
    unsigned* s1 = s_s1[sl];

    // ---- conv1 (27-term XNOR) + threshold + pool(min) -> s1[10][10], bit = oc ----
    for (int py = 0; py < 10; ++py) {
        unsigned rows[12];
#pragma unroll
        for (int c = 0; c < 3; ++c)
#pragma unroll
            for (int k = 0; k < 4; ++k) rows[c * 4 + k] = pin[c * 22 + 2 * py + k];
        // lane owns cells with (py*10+px) % 8 == r  ->  px ≡ (r + 6*py) (mod 8)
        int px0 = (r + 6 * py) & 7;
        for (int px = px0; px < 10; px += 8) {
            unsigned key[4];
#pragma unroll
            for (int yy = 0; yy < 2; ++yy)
#pragma unroll
                for (int xx = 0; xx < 2; ++xx) {
                    int x0 = 2 * px + xx;
                    unsigned k = 0;
#pragma unroll
                    for (int c = 0; c < 3; ++c)
#pragma unroll
                        for (int dy = 0; dy < 3; ++dy)
                            k |= ((rows[c * 4 + yy + dy] >> x0) & 7u) << (c * 9 + dy * 3);
                    key[yy * 2 + xx] = k;
                }
            unsigned acc = 0;
#pragma unroll
            for (int oc = 0; oc < 32; ++oc) {
                unsigned w = s_w1[oc];
                int m = min(min((int)__popc(key[0] ^ w), (int)__popc(key[1] ^ w)),
                            min((int)__popc(key[2] ^ w), (int)__popc(key[3] ^ w)));
                acc |= (m <= s_T1[oc]) ? (1u << oc) : 0u;
            }
            s1[py * 10 + px] = acc;
        }
    }
    __syncwarp();

    // ---- conv2 (288-term, CSA popcount): lane owns pooled row r>>1, 2 cells, all 32 oc ----
    {
        const int pr = r >> 1;            // 0..3
        const int pcb = (r & 1) * 2;      // 0 or 2
        unsigned R[4][6];                 // rows 2pr..2pr+3, cols 2*pcb .. 2*pcb+5
#pragma unroll
        for (int y = 0; y < 4; ++y)
#pragma unroll
            for (int xx = 0; xx < 6; ++xx) R[y][xx] = s1[(2 * pr + y) * 10 + 2 * pcb + xx];
        unsigned acc0 = 0u, acc1 = 0u;
#pragma unroll 2
        for (int oc = 0; oc < 32; ++oc) {
            unsigned w[9];
#pragma unroll
            for (int j = 0; j < 9; ++j) w[j] = s_w2[oc * 9 + j];
            int T = s_T2[oc];
#pragma unroll
            for (int cell = 0; cell < 2; ++cell) {
                const int cb = 2 * cell;
                int c0 = popc9(R[0][cb] ^ w[0], R[0][cb + 1] ^ w[1], R[0][cb + 2] ^ w[2],
                               R[1][cb] ^ w[3], R[1][cb + 1] ^ w[4], R[1][cb + 2] ^ w[5],
                               R[2][cb] ^ w[6], R[2][cb + 1] ^ w[7], R[2][cb + 2] ^ w[8]);
                int c1 = popc9(R[0][cb + 1] ^ w[0], R[0][cb + 2] ^ w[1], R[0][cb + 3] ^ w[2],
                               R[1][cb + 1] ^ w[3], R[1][cb + 2] ^ w[4], R[1][cb + 3] ^ w[5],
                               R[2][cb + 1] ^ w[6], R[2][cb + 2] ^ w[7], R[2][cb + 3] ^ w[8]);
                int c2 = popc9(R[1][cb] ^ w[0], R[1][cb + 1] ^ w[1], R[1][cb + 2] ^ w[2],
                               R[2][cb] ^ w[3], R[2][cb + 1] ^ w[4], R[2][cb + 2] ^ w[5],
                               R[3][cb] ^ w[6], R[3][cb + 1] ^ w[7], R[3][cb + 2] ^ w[8]);
                int c3 = popc9(R[1][cb + 1] ^ w[0], R[1][cb + 2] ^ w[1], R[1][cb + 3] ^ w[2],
                               R[2][cb + 1] ^ w[3], R[2][cb + 2] ^ w[4], R[2][cb + 3] ^ w[5],
                               R[3][cb + 1] ^ w[6], R[3][cb + 2] ^ w[7], R[3][cb + 3] ^ w[8]);
                int m = min(min(c0, c1), min(c2, c3));
                if (cell == 0) acc0 |= (m <= T) ? (1u << oc) : 0u;
                else           acc1 |= (m <= T) ? (1u << oc) : 0u;
            }
        }
        s_s2[sl][pr * 4 + pcb]     = acc0;
        s_s2[sl][pr * 4 + pcb + 1] = acc1;
    }
    __syncwarp();

    // ---- conv3 (288-term, CSA popcount, 64 oc; 8 per lane) + pool -> 64 bits (a0,a1) ----
    unsigned S2[16];
#pragma unroll
    for (int i = 0; i < 16; ++i) S2[i] = s_s2[sl][i];

    unsigned p0 = 0u, p1 = 0u;
    const int ocb3 = r * 8;
#pragma unroll 1
    for (int k = 0; k < 8; ++k) {
        int oc = ocb3 + k;
        unsigned w[9];
#pragma unroll
        for (int j = 0; j < 9; ++j) w[j] = s_w3[oc * 9 + j];
        int c0 = popc9(S2[0] ^ w[0], S2[1] ^ w[1], S2[2] ^ w[2],
                       S2[4] ^ w[3], S2[5] ^ w[4], S2[6] ^ w[5],
                       S2[8] ^ w[6], S2[9] ^ w[7], S2[10] ^ w[8]);
        int c1 = popc9(S2[1] ^ w[0], S2[2] ^ w[1], S2[3] ^ w[2],
                       S2[5] ^ w[3], S2[6] ^ w[4], S2[7] ^ w[5],
                       S2[9] ^ w[6], S2[10] ^ w[7], S2[11] ^ w[8]);
        int c2 = popc9(S2[4] ^ w[0], S2[5] ^ w[1], S2[6] ^ w[2],
                       S2[8] ^ w[3], S2[9] ^ w[4], S2[10] ^ w[5],
                       S2[12] ^ w[6], S2[13] ^ w[7], S2[14] ^ w[8]);
        int c3 = popc9(S2[5] ^ w[0], S2[6] ^ w[1], S2[7] ^ w[2],
                       S2[9] ^ w[3], S2[10] ^ w[4], S2[11] ^ w[5],
                       S2[13] ^ w[6], S2[14] ^ w[7], S2[15] ^ w[8]);
        int m = min(min(c0, c1), min(c2, c3));
        unsigned mbit = (m <= s_T3[oc]) ? (1u << (oc & 31)) : 0u;
        if (r < 4) p0 |= mbit; else p1 |= mbit;
    }
    unsigned a0 = p0, a1 = p1;
    a0 |= __shfl_xor_sync(0xFFFFFFFFu, a0, 1); a0 |= __shfl_xor_sync(0xFFFFFFFFu, a0, 2);
    a0 |= __shfl_xor_sync(0xFFFFFFFFu, a0, 4);
    a1 |= __shfl_xor_sync(0xFFFFFFFFu, a1, 1); a1 |= __shfl_xor_sync(0xFFFFFFFFu, a1, 2);
    a1 |= __shfl_xor_sync(0xFFFFFFFFu, a1, 4);

    // ---- fc1 (binary 64-dot) + bn4 + hardtanh, fused with the two float heads ----
    float t0 = 0.f, t1 = 0.f, u0 = 0.f, u1 = 0.f, u2 = 0.f, u3 = 0.f;
    const int jb = r * 16;
#pragma unroll 4
    for (int k = 0; k < 16; ++k) {
        int j = jb + k;
        int cnt = __popc(a0 ^ s_fc1[2 * j]) + __popc(a1 ^ s_fc1[2 * j + 1]);
        float sv = (float)(64 - 2 * cnt);
        float h = fminf(1.f, fmaxf(-1.f, fmaf(sv, s_a4[j], s_c4[j])));
        t0 = fmaf(h, s_f2[j], t0);
        t1 = fmaf(h, s_f2[128 + j], t1);
        u0 = fmaf(h, s_f3[j], u0);
        u1 = fmaf(h, s_f3[128 + j], u1);
        u2 = fmaf(h, s_f3[256 + j], u2);
        u3 = fmaf(h, s_f3[384 + j], u3);
    }
#pragma unroll
    for (int d = 1; d < 8; d <<= 1) {
        t0 += __shfl_xor_sync(0xFFFFFFFFu, t0, d);
        t1 += __shfl_xor_sync(0xFFFFFFFFu, t1, d);
        u0 += __shfl_xor_sync(0xFFFFFFFFu, u0, d);
        u1 += __shfl_xor_sync(0xFFFFFFFFu, u1, d);
        u2 += __shfl_xor_sync(0xFFFFFFFFu, u2, d);
        u3 += __shfl_xor_sync(0xFFFFFFFFu, u3, d);
    }
    if (r == 0) {
        float z0 = fmaf(t0, s_head[0], s_head[2]);
        float z1 = fmaf(t1, s_head[1], s_head[3]);
        float mx = fmaxf(z0, z1);
        float e0 = expf(z0 - mx), e1 = expf(z1 - mx);
        float is = 1.f / (e0 + e1);
        out[2 * s]     = e0 * is;
        out[2 * s + 1] = e1 * is;
        float* o2 = out + (size_t)2 * B;
        o2[4 * s]     = fmaf(u0, s_head[4], s_head[8]);
        o2[4 * s + 1] = fmaf(u1, s_head[5], s_head[9]);
        o2[4 * s + 2] = fmaf(u2, s_head[6], s_head[10]);
        o2[4 * s + 3] = fmaf(u3, s_head[7], s_head[11]);
    }
}

// ---------------- launch ----------------
extern "C" void kernel_launch(void* const* d_in, const int* in_sizes, int n_in,
                              void* d_out, int out_size) {
    (void)n_in; (void)out_size;
    const float* x    = (const float*)d_in[0];
    const float* w1   = (const float*)d_in[1];
    const float* w2   = (const float*)d_in[2];
    const float* w3   = (const float*)d_in[3];
    const float* wfc1 = (const float*)d_in[4];
    const float* wfc2 = (const float*)d_in[5];
    const float* wfc3 = (const float*)d_in[6];
    const float* bn1  = (const float*)d_in[7];
    const float* bn2  = (const float*)d_in[8];
    const float* bn3  = (const float*)d_in[9];
    const float* bn4  = (const float*)d_in[10];
    const float* bn5  = (const float*)d_in[11];
    const float* bn6  = (const float*)d_in[12];

    int B = in_sizes[0] / 1452;  // 3*22*22
    if (B > MAXB) B = MAXB;

    prep_kernel<<<8, 256>>>(w1, w2, w3, wfc1, bn1, bn2, bn3, bn4, bn5, bn6);
    main_kernel<<<(B * 8 + 127) / 128, 128>>>(x, wfc2, wfc3, (float*)d_out, B);
}